// round 10
// baseline (speedup 1.0000x reference)
#include <cuda_runtime.h>
#include <cstdint>

#define DEVINL __device__ __forceinline__

static constexpr int IN_F   = 256;
static constexpr int OUT_F  = 64;
static constexpr int M_TILE = 128;
static constexpr int NCHUNK = 64;      // K chunks of 64 (4 inputs x 16 slots)

// smem layout (bytes from 1024-aligned dynamic base)
static constexpr int SM_X    = 0;                 // x panel: 16 cols x 130 pitch = 8320B
static constexpr int SM_A0   = 9216;              // A frags buf0: 32KB
static constexpr int SM_A1   = SM_A0 + 32768;     // 41984
static constexpr int SM_B0   = SM_A1 + 32768;     // 74752
static constexpr int SM_B1   = SM_B0 + 16384;     // 91136
static constexpr int SMEM_SZ = SM_B1 + 16384 + 1024; // 108544; 2 CTAs/SM

__device__ float g_B[NCHUNK * 4096];   // 1MB pre-fragmented tf32 weights

DEVINL uint32_t smem_u32(const void* p) {
    uint32_t a;
    asm("{ .reg .u64 t; cvta.to.shared.u64 t, %1; cvt.u32.u64 %0, t; }" : "=r"(a) : "l"(p));
    return a;
}
DEVINL uint32_t to_tf32(float f) {
    uint32_t u; asm("cvt.rna.tf32.f32 %0, %1;" : "=r"(u) : "f"(f)); return u;
}
DEVINL void sts128(uint32_t a, uint32_t x, uint32_t y, uint32_t z, uint32_t w) {
    asm volatile("st.shared.v4.b32 [%0], {%1,%2,%3,%4};" :: "r"(a), "r"(x), "r"(y), "r"(z), "r"(w) : "memory");
}
DEVINL void sts32(uint32_t a, uint32_t v) {
    asm volatile("st.shared.b32 [%0], %1;" :: "r"(a), "r"(v) : "memory");
}
DEVINL float lds32f(uint32_t a) {
    float v; asm volatile("ld.shared.f32 %0, [%1];" : "=f"(v) : "r"(a)); return v;
}
DEVINL void lds64f(uint32_t a, float& x, float& y) {
    asm volatile("ld.shared.v2.f32 {%0,%1}, [%2];" : "=f"(x), "=f"(y) : "r"(a));
}
DEVINL void lds128(uint32_t a, uint32_t& x, uint32_t& y, uint32_t& z, uint32_t& w) {
    asm volatile("ld.shared.v4.b32 {%0,%1,%2,%3}, [%4];" : "=r"(x), "=r"(y), "=r"(z), "=r"(w) : "r"(a));
}
DEVINL void lds64(uint32_t a, uint32_t& x, uint32_t& y) {
    asm volatile("ld.shared.v2.b32 {%0,%1}, [%2];" : "=r"(x), "=r"(y) : "r"(a));
}
DEVINL void cpasync16(uint32_t dst, const void* src) {
    asm volatile("cp.async.cg.shared.global [%0], [%1], 16;" :: "r"(dst), "l"(src) : "memory");
}
DEVINL void cp_commit() { asm volatile("cp.async.commit_group;" ::: "memory"); }
DEVINL void cp_wait0()  { asm volatile("cp.async.wait_group 0;" ::: "memory"); }
DEVINL void bar_sync(int id, int cnt) {
    asm volatile("bar.sync %0, %1;" :: "r"(id), "r"(cnt) : "memory");
}
DEVINL void bar_arrive(int id, int cnt) {
    asm volatile("bar.arrive %0, %1;" :: "r"(id), "r"(cnt) : "memory");
}
DEVINL void membar_cta() { asm volatile("membar.cta;" ::: "memory"); }
DEVINL void mma8(float* d, const uint32_t* A, uint32_t b0, uint32_t b1) {
    asm volatile(
        "mma.sync.aligned.m16n8k8.row.col.f32.tf32.tf32.f32 "
        "{%0,%1,%2,%3}, {%4,%5,%6,%7}, {%8,%9}, {%0,%1,%2,%3};"
        : "+f"(d[0]), "+f"(d[1]), "+f"(d[2]), "+f"(d[3])
        : "r"(A[0]), "r"(A[1]), "r"(A[2]), "r"(A[3]), "r"(b0), "r"(b1));
}
DEVINL uint32_t sw128(uint32_t o) { return o ^ ((o >> 3) & 0x70u); }

// ---- pre-kernel: weights -> tf32 B fragments ----
// layout: [chunk][q(0..7)][nb(0..7)][lane(0..31)][reg(0..1)]
__global__ void kan_expand(const float* __restrict__ bw, const float* __restrict__ sw) {
    int fi = blockIdx.x * 256 + threadIdx.x;     // 0 .. 262143
    int r    = fi & 4095;
    int reg  = r & 1;
    int lane = (r >> 1) & 31;
    int nb   = (r >> 6) & 7;
    int q    = (r >> 9) & 7;
    int c    = fi >> 12;
    int kloc = q * 8 + (lane & 3) + reg * 4;
    int isub = kloc >> 4, slot = kloc & 15;
    int i = c * 4 + isub;
    int o = nb * 8 + (lane >> 2);
    float v = 0.0f;
    if (slot == 0)       v = bw[o * IN_F + i];
    else if (slot <= 13) v = sw[(o * IN_F + i) * 13 + (slot - 1)];
    g_B[fi] = __uint_as_float(to_tf32(v));
}

// produce A fragments of chunk cc for pair-slot (mb, isub, g): rows mb*16+g, +8
DEVINL void produce_A(uint32_t sb, uint32_t aBase, int cc, int mb, int isub, int g) {
    const uint32_t xcol = sb + SM_X + (uint32_t)(((cc & 3) * 4 + isub) * 130) * 4u;
    const float xv0 = lds32f(xcol + (uint32_t)(mb * 16 + g) * 4u);
    const float xv1 = lds32f(xcol + (uint32_t)(mb * 16 + g + 8) * 4u);

    uint32_t silu[2], bt[2][4]; int mm[2];
    #pragma unroll
    for (int rr = 0; rr < 2; ++rr) {
        const float xv = rr ? xv1 : xv0;
        silu[rr] = to_tf32(__fdividef(xv, 1.0f + __expf(-xv)));
        const float xc = fminf(fmaxf(xv, -2.5f), 2.5f);
        const float u  = (xc + 3.2f) * 2.5f;
        const float mf = floorf(u);
        mm[rr] = (int)mf;
        const float t = u - mf, t2 = t * t, t3 = t2 * t, omt = 1.0f - t;
        const float i6 = 1.0f / 6.0f;
        bt[rr][0] = to_tf32(i6 * omt * omt * omt);
        bt[rr][1] = to_tf32(i6 * (3.0f * t3 - 6.0f * t2 + 4.0f));
        bt[rr][2] = to_tf32(i6 * (-3.0f * t3 + 3.0f * t2 + 3.0f * t + 1.0f));
        bt[rr][3] = to_tf32(i6 * t3);
    }
    #pragma unroll
    for (int h = 0; h < 2; ++h) {        // q = 2*isub + h, slots 8h..8h+7
        const int q = 2 * isub + h;
        uint32_t v[2][2][4];             // [row][k-half][t]
        #pragma unroll
        for (int rr = 0; rr < 2; ++rr) {
            const int m = mm[rr];
            #pragma unroll
            for (int t = 0; t < 4; ++t) {
                const int k0 = (t + 2 - m) & 3;
                const uint32_t bsel =
                    k0 == 0 ? bt[rr][0] : k0 == 1 ? bt[rr][1] :
                    k0 == 2 ? bt[rr][2] : bt[rr][3];
                #pragma unroll
                for (int ph = 0; ph < 2; ++ph) {
                    const int s = 8 * h + t + 4 * ph;
                    const int sidx = s + 2 - m;
                    uint32_t val = ((unsigned)sidx <= 3u && s <= 13) ? bsel : 0u;
                    if (s == 0) val = silu[rr];
                    v[rr][ph][t] = val;
                }
            }
        }
        #pragma unroll
        for (int t = 0; t < 4; ++t) {
            const uint32_t off = (uint32_t)(((mb * 8 + q) * 32 + g * 4 + t)) * 16u;
            sts128(aBase + sw128(off), v[0][0][t], v[1][0][t], v[0][1][t], v[1][1][t]);
        }
    }
}

// ---- main kernel: warp-specialized producer/consumer ----
__global__ void __launch_bounds__(384, 2)
kan_main(const float* __restrict__ x, float* __restrict__ out) {
    extern __shared__ char smem_raw[];
    const uint32_t sb = (smem_u32(smem_raw) + 1023u) & ~1023u;
    const int tid = threadIdx.x, wid = tid >> 5, lane = tid & 31;
    const int rowBase = blockIdx.x * M_TILE;

    if (wid < 8) {
        // ================= CONSUMER: warps 0..7 =================
        const int gw = wid >> 2, wg = wid & 3;   // k-half, m-slice
        float acc[2][8][4];
        #pragma unroll
        for (int a = 0; a < 2; ++a)
            #pragma unroll
            for (int b = 0; b < 8; ++b)
                #pragma unroll
                for (int k = 0; k < 4; ++k) acc[a][b][k] = 0.0f;

        bar_arrive(1, 384);   // free[0]
        bar_arrive(2, 384);   // free[1]

        for (int c = 0; c < NCHUNK; ++c) {
            const int b = c & 1;
            bar_sync(3 + b, 384);             // wait full[b]
            const uint32_t aB = sb + (b ? SM_A1 : SM_A0);
            const uint32_t bB = sb + (b ? SM_B1 : SM_B0);
            #pragma unroll
            for (int qi = 0; qi < 4; ++qi) {
                const int q = gw * 4 + qi;
                uint32_t A0[4], A1[4];
                lds128(aB + sw128((uint32_t)((((2 * wg) * 8 + q) * 32 + lane)) * 16u),
                       A0[0], A0[1], A0[2], A0[3]);
                lds128(aB + sw128((uint32_t)((((2 * wg + 1) * 8 + q) * 32 + lane)) * 16u),
                       A1[0], A1[1], A1[2], A1[3]);
                #pragma unroll
                for (int nb = 0; nb < 8; ++nb) {
                    uint32_t b0, b1;
                    lds64(bB + (uint32_t)(((q * 8 + nb) * 32 + lane)) * 8u, b0, b1);
                    mma8(acc[0][nb], A0, b0, b1);
                    mma8(acc[1][nb], A1, b0, b1);
                }
            }
            bar_arrive(1 + b, 384);           // free[b]
        }

        // ---- epilogue: reduce K-halves (consumer-only barrier id 6) ----
        const uint32_t ex = sb + SM_A0;
        if (gw == 1) {
            #pragma unroll
            for (int mbl = 0; mbl < 2; ++mbl)
                #pragma unroll
                for (int nb = 0; nb < 8; ++nb)
                    #pragma unroll
                    for (int k = 0; k < 4; ++k) {
                        int row = wg * 32 + mbl * 16 + (lane >> 2) + ((k & 2) ? 8 : 0);
                        int col = nb * 8 + (lane & 3) * 2 + (k & 1);
                        sts32(ex + (uint32_t)(row * 64 + col) * 4u,
                              __float_as_uint(acc[mbl][nb][k]));
                    }
        }
        bar_sync(6, 256);
        if (gw == 0) {
            #pragma unroll
            for (int mbl = 0; mbl < 2; ++mbl)
                #pragma unroll
                for (int nb = 0; nb < 8; ++nb)
                    #pragma unroll
                    for (int kr = 0; kr < 2; ++kr) {
                        int row = wg * 32 + mbl * 16 + (lane >> 2) + kr * 8;
                        int col = nb * 8 + (lane & 3) * 2;
                        float p0, p1;
                        lds64f(ex + (uint32_t)(row * 64 + col) * 4u, p0, p1);
                        float2 v;
                        v.x = acc[mbl][nb][kr * 2 + 0] + p0;
                        v.y = acc[mbl][nb][kr * 2 + 1] + p1;
                        *reinterpret_cast<float2*>(
                            out + (size_t)(rowBase + row) * OUT_F + col) = v;
                    }
        }
    } else {
        // ================= PRODUCER: warps 8..11 =================
        const int ptid = tid - 256;          // 0..127
        for (int c = 0; c < NCHUNK; ++c) {
            const int b = c & 1;
            if ((c & 3) == 0) {              // refresh x panel (producers only)
                bar_sync(5, 128);
                #pragma unroll
                for (int u = 0; u < 4; ++u) {
                    int v = ptid + 128 * u;  // 512 float4 slots
                    int pr = v >> 2, q4 = v & 3;
                    const float4 xv = *reinterpret_cast<const float4*>(
                        x + (size_t)(rowBase + pr) * IN_F + c * 4 + 4 * q4);
                    uint32_t a0 = sb + SM_X + (uint32_t)((4 * q4) * 130 + pr) * 4u;
                    sts32(a0,             __float_as_uint(xv.x));
                    sts32(a0 + 130u * 4u, __float_as_uint(xv.y));
                    sts32(a0 + 260u * 4u, __float_as_uint(xv.z));
                    sts32(a0 + 390u * 4u, __float_as_uint(xv.w));
                }
                bar_sync(5, 128);
            }
            bar_sync(1 + b, 384);            // wait free[b]
            // stage B(c) via cp.async
            {
                const char* src = (const char*)(g_B + c * 4096);
                const uint32_t bdst = sb + (b ? SM_B1 : SM_B0);
                #pragma unroll
                for (int u = 0; u < 8; ++u) {
                    int v = ptid + 128 * u;  // 1024 slots of 16B
                    cpasync16(bdst + (uint32_t)v * 16u, src + (size_t)v * 16u);
                }
                cp_commit();
            }
            // produce A(c): 2 pair-slots per thread
            const uint32_t aBase = sb + (b ? SM_A1 : SM_A0);
            #pragma unroll
            for (int j = 0; j < 2; ++j) {
                const int slot = ptid + 128 * j;      // 0..255
                produce_A(sb, aBase, c, slot >> 5, (slot >> 3) & 3, slot & 7);
            }
            cp_wait0();
            membar_cta();
            bar_arrive(3 + b, 384);          // full[b]
        }
    }
}

extern "C" void kernel_launch(void* const* d_in, const int* in_sizes, int n_in,
                              void* d_out, int out_size) {
    const float* x  = (const float*)d_in[0];
    const float* bw = (const float*)d_in[1];
    const float* sw = (const float*)d_in[2];
    float* out = (float*)d_out;
    cudaFuncSetAttribute(kan_main, cudaFuncAttributeMaxDynamicSharedMemorySize, SMEM_SZ);
    kan_expand<<<1024, 256>>>(bw, sw);
    kan_main<<<65536 / M_TILE, 384, SMEM_SZ>>>(x, out);
}

// round 11
// speedup vs baseline: 2.4953x; 2.4953x over previous
#include <cuda_runtime.h>
#include <cstdint>

#define DEVINL __device__ __forceinline__

static constexpr int IN_F   = 256;
static constexpr int OUT_F  = 64;
static constexpr int M_TILE = 128;
static constexpr int NCHUNK = 64;      // K chunks: 4 inputs x 16 slots (64 f16)

// smem layout (bytes from 1024-aligned dynamic base)
static constexpr int SM_X    = 0;      // x panel: 16 cols x 130 pitch fp32 = 8320B
static constexpr int SM_A    = 8448;   // A tile: 4 i * 128 rows * 32B = 16KB
static constexpr int SM_B    = SM_A + 16384;   // B frags: 8KB
static constexpr int SMEM_SZ = SM_B + 8192 + 1024;  // ~33.6KB -> 3 CTAs/SM

__device__ uint2 g_B[NCHUNK * 4 * 8 * 32];   // 512KB pre-packed f16 B fragments

DEVINL uint32_t smem_u32(const void* p) {
    uint32_t a;
    asm("{ .reg .u64 t; cvta.to.shared.u64 t, %1; cvt.u32.u64 %0, t; }" : "=r"(a) : "l"(p));
    return a;
}
DEVINL uint16_t f2h(float f) {
    uint16_t h; asm("cvt.rn.f16.f32 %0, %1;" : "=h"(h) : "f"(f)); return h;
}
DEVINL void sts128(uint32_t a, uint32_t x, uint32_t y, uint32_t z, uint32_t w) {
    asm volatile("st.shared.v4.b32 [%0], {%1,%2,%3,%4};" :: "r"(a), "r"(x), "r"(y), "r"(z), "r"(w) : "memory");
}
DEVINL void sts32(uint32_t a, uint32_t v) {
    asm volatile("st.shared.b32 [%0], %1;" :: "r"(a), "r"(v) : "memory");
}
DEVINL void sts16(uint32_t a, uint16_t v) {
    asm volatile("st.shared.u16 [%0], %1;" :: "r"(a), "h"(v) : "memory");
}
DEVINL float lds32f(uint32_t a) {
    float v; asm volatile("ld.shared.f32 %0, [%1];" : "=f"(v) : "r"(a)); return v;
}
DEVINL void lds64(uint32_t a, uint32_t& x, uint32_t& y) {
    asm volatile("ld.shared.v2.b32 {%0,%1}, [%2];" : "=r"(x), "=r"(y) : "r"(a));
}
DEVINL void ldsm4(uint32_t a, uint32_t& r0, uint32_t& r1, uint32_t& r2, uint32_t& r3) {
    asm volatile("ldmatrix.sync.aligned.m8n8.x4.shared.b16 {%0,%1,%2,%3}, [%4];"
                 : "=r"(r0), "=r"(r1), "=r"(r2), "=r"(r3) : "r"(a));
}
DEVINL void cpasync16(uint32_t dst, const void* src) {
    asm volatile("cp.async.cg.shared.global [%0], [%1], 16;" :: "r"(dst), "l"(src) : "memory");
}
DEVINL void cp_commit() { asm volatile("cp.async.commit_group;" ::: "memory"); }
DEVINL void cp_wait0()  { asm volatile("cp.async.wait_group 0;" ::: "memory"); }
DEVINL void mma16(float* d, const uint32_t* A, uint32_t b0, uint32_t b1) {
    asm volatile(
        "mma.sync.aligned.m16n8k16.row.col.f32.f16.f16.f32 "
        "{%0,%1,%2,%3}, {%4,%5,%6,%7}, {%8,%9}, {%0,%1,%2,%3};"
        : "+f"(d[0]), "+f"(d[1]), "+f"(d[2]), "+f"(d[3])
        : "r"(A[0]), "r"(A[1]), "r"(A[2]), "r"(A[3]), "r"(b0), "r"(b1));
}

// ---- pre-kernel: weights -> packed f16 B fragments ----
// entry e = ((c*4 + kq)*8 + nb)*32 + lane ; kq == input-within-chunk i
// b0 = {slot k0, k0+1}, b1 = {k0+8, k0+9}, k0 = 2*(lane&3), n = nb*8 + lane/4
__global__ void kan_expand(const float* __restrict__ bw, const float* __restrict__ sw) {
    int e = blockIdx.x * 256 + threadIdx.x;      // 0..65535
    int lane = e & 31, nb = (e >> 5) & 7, kq = (e >> 8) & 3, c = e >> 10;
    int n = nb * 8 + (lane >> 2);
    int k0 = 2 * (lane & 3);
    int i = c * 4 + kq;
    auto wv = [&](int s) -> float {
        if (s == 0) return bw[n * IN_F + i];
        if (s <= 13) return sw[(n * IN_F + i) * 13 + (s - 1)];
        return 0.0f;
    };
    uint32_t b0 = (uint32_t)f2h(wv(k0))     | ((uint32_t)f2h(wv(k0 + 1)) << 16);
    uint32_t b1 = (uint32_t)f2h(wv(k0 + 8)) | ((uint32_t)f2h(wv(k0 + 9)) << 16);
    g_B[e] = make_uint2(b0, b1);
}

// produce one (row, i) 16-slot f16 feature row: zeros + silu + <=4 taps
DEVINL void produce_pair(uint32_t sb, int cc, int row, int i) {
    const float xv = lds32f(sb + SM_X + (uint32_t)((((cc & 3) * 4 + i) * 130) + row) * 4u);
    const float sl = __fdividef(xv, 1.0f + __expf(-xv));
    const float xc = fminf(fmaxf(xv, -2.5f), 2.5f);
    const float u  = (xc + 3.2f) * 2.5f;
    const float mf = floorf(u);
    const int   m  = (int)mf;
    const float t = u - mf, t2 = t * t, t3 = t2 * t, omt = 1.0f - t;
    const float i6 = 1.0f / 6.0f;
    uint16_t hs = f2h(sl);
    uint16_t hb[4];
    hb[0] = f2h(i6 * omt * omt * omt);
    hb[1] = f2h(i6 * (3.0f * t3 - 6.0f * t2 + 4.0f));
    hb[2] = f2h(i6 * (-3.0f * t3 + 3.0f * t2 + 3.0f * t + 1.0f));
    hb[3] = f2h(i6 * t3);

    const uint32_t base = sb + SM_A + (uint32_t)i * 4096u + (uint32_t)row * 32u;
    const uint32_t sw   = ((uint32_t)(row >> 2) & 1u) << 4;   // granule swizzle
    sts128(base,      0u, 0u, 0u, 0u);
    sts128(base + 16, 0u, 0u, 0u, 0u);
    sts16(base + sw, hs);                                     // slot 0 = silu
    #pragma unroll
    for (int k = 0; k < 4; ++k) {
        const int s = m - 2 + k;                              // tap slot
        if (s >= 1 && s <= 13)
            sts16(base + ((((uint32_t)s >> 3) << 4) ^ sw) + (uint32_t)(s & 7) * 2u, hb[k]);
    }
}

// ---- main kernel: bulk-synchronous, fp16 mma, ldmatrix A ----
__global__ void __launch_bounds__(256, 3)
kan_main(const float* __restrict__ x, float* __restrict__ out) {
    extern __shared__ char smem_raw[];
    const uint32_t sb = (smem_u32(smem_raw) + 1023u) & ~1023u;
    const int tid = threadIdx.x, wid = tid >> 5, lane = tid & 31;
    const int rowBase = blockIdx.x * M_TILE;

    // ldmatrix per-lane address base (constant across chunks, +i*4096 varies)
    const int rin = lane & 15, chh = lane >> 4;
    const int grow = wid * 16 + rin;
    const uint32_t ldsm_off = sb + SM_A + (uint32_t)grow * 32u
                            + (((uint32_t)(chh ^ ((grow >> 2) & 1))) << 4);

    // producer role
    const int prow = tid & 127, pi0 = tid >> 7;   // i = pi0, pi0+2

    float acc[8][4];
    #pragma unroll
    for (int nb = 0; nb < 8; ++nb)
        #pragma unroll
        for (int k = 0; k < 4; ++k) acc[nb][k] = 0.0f;

    for (int c = 0; c < NCHUNK; ++c) {
        if ((c & 3) == 0) {   // refresh x panel (16 cols, transposed, pitch 130)
            __syncthreads();
            #pragma unroll
            for (int u2 = 0; u2 < 2; ++u2) {
                int v = tid + 256 * u2;          // 512 float4 slots
                int pr = v >> 2, q4 = v & 3;
                const float4 xv = *reinterpret_cast<const float4*>(
                    x + (size_t)(rowBase + pr) * IN_F + c * 4 + 4 * q4);
                uint32_t a0 = sb + SM_X + (uint32_t)((4 * q4) * 130 + pr) * 4u;
                sts32(a0,             __float_as_uint(xv.x));
                sts32(a0 + 130u * 4u, __float_as_uint(xv.y));
                sts32(a0 + 260u * 4u, __float_as_uint(xv.z));
                sts32(a0 + 390u * 4u, __float_as_uint(xv.w));
            }
            __syncthreads();
        }

        // stage B chunk (8KB) via cp.async
        {
            const char* src = (const char*)(g_B) + (size_t)c * 8192;
            #pragma unroll
            for (int u = 0; u < 2; ++u) {
                int v = tid + 256 * u;           // 512 x 16B
                cpasync16(sb + SM_B + (uint32_t)v * 16u, src + (size_t)v * 16u);
            }
            cp_commit();
        }

        // produce A: 2 (row,i) pairs per thread (512 pairs total)
        produce_pair(sb, c, prow, pi0);
        produce_pair(sb, c, prow, pi0 + 2);

        cp_wait0();
        __syncthreads();

        // mma: warp wid owns rows wid*16..+15; all 4 i-blocks (K=16 each)
        #pragma unroll
        for (int i = 0; i < 4; ++i) {
            uint32_t A[4];
            ldsm4(ldsm_off + (uint32_t)i * 4096u, A[0], A[1], A[2], A[3]);
            #pragma unroll
            for (int nb = 0; nb < 8; ++nb) {
                uint32_t b0, b1;
                lds64(sb + SM_B + (uint32_t)(((i * 8 + nb) * 32 + lane)) * 8u, b0, b1);
                mma16(acc[nb], A, b0, b1);
            }
        }
        __syncthreads();
    }

    // ---- epilogue: direct C-fragment stores ----
    const int r0  = wid * 16 + (lane >> 2);
    const int col = 2 * (lane & 3);
    #pragma unroll
    for (int nb = 0; nb < 8; ++nb) {
        float2 v0; v0.x = acc[nb][0]; v0.y = acc[nb][1];
        float2 v1; v1.x = acc[nb][2]; v1.y = acc[nb][3];
        *reinterpret_cast<float2*>(out + (size_t)(rowBase + r0) * OUT_F + nb * 8 + col) = v0;
        *reinterpret_cast<float2*>(out + (size_t)(rowBase + r0 + 8) * OUT_F + nb * 8 + col) = v1;
    }
}

extern "C" void kernel_launch(void* const* d_in, const int* in_sizes, int n_in,
                              void* d_out, int out_size) {
    const float* x  = (const float*)d_in[0];
    const float* bw = (const float*)d_in[1];
    const float* sw = (const float*)d_in[2];
    float* out = (float*)d_out;
    cudaFuncSetAttribute(kan_main, cudaFuncAttributeMaxDynamicSharedMemorySize, SMEM_SZ);
    kan_expand<<<256, 256>>>(bw, sw);
    kan_main<<<65536 / M_TILE, 256, SMEM_SZ>>>(x, out);
}